// round 2
// baseline (speedup 1.0000x reference)
#include <cuda_runtime.h>

// ---------------- problem constants (fixed by the dataset) ----------------
#define N_ATOMS 100000
#define DIN     120
#define HID     128
#define NMOL    2000
#define NELEM   3
#define TILE    16          // atoms per block
#define NTHR    128         // threads per block (4 warps)
#define PTOT    (N_ATOMS + 48)          // padded perm length (<= +3*(TILE-1))
#define NBLK    ((PTOT + TILE - 1) / TILE)

// ---------------- device scratch (static: no allocations allowed) --------
__device__ float g_flat_d[N_ATOMS * DIN];   // dE/dfp, 48 MB
__device__ int   perm_d[PTOT];
__device__ int   counts_d[NELEM];
__device__ int   cursor_d[NELEM];

__device__ __forceinline__ int elem_of(int z) {
    return (z == 1) ? 0 : ((z == 6) ? 1 : 2);
}

// ---------------- init: zero outputs, fill perm with -1, zero counters ---
__global__ void k_init(float* __restrict__ out) {
    int i = blockIdx.x * blockDim.x + threadIdx.x;
    if (i < NMOL + 3 * N_ATOMS) out[i] = 0.f;
    if (i < PTOT)  perm_d[i] = -1;
    if (i < NELEM) { counts_d[i] = 0; cursor_d[i] = 0; }
}

__global__ void k_count(const int* __restrict__ z) {
    int i = blockIdx.x * blockDim.x + threadIdx.x;
    if (i < N_ATOMS) atomicAdd(&counts_d[elem_of(z[i])], 1);
}

__global__ void k_offsets() {
    // single thread: exclusive scan of rounded-up counts -> cursors
    int r0 = (counts_d[0] + TILE - 1) / TILE * TILE;
    int r1 = (counts_d[1] + TILE - 1) / TILE * TILE;
    cursor_d[0] = 0;
    cursor_d[1] = r0;
    cursor_d[2] = r0 + r1;
}

__global__ void k_build(const int* __restrict__ z) {
    int i = blockIdx.x * blockDim.x + threadIdx.x;
    if (i < N_ATOMS) {
        int e = elem_of(z[i]);
        int p = atomicAdd(&cursor_d[e], 1);
        if (p >= 0 && p < PTOT) perm_d[p] = i;   // defensive clamp
    }
}

// ---------------- fused MLP forward + backward ----------------------------
// Thread map: cg = tid&31 (H-column group), ag = tid>>5 (atom group of 4).
// Forward: thread owns cols cg*4..cg*4+3 (float4 weight loads, coalesced).
// Backward: thread owns cols cg + 32*mm (conflict-free transposed smem reads).

__device__ __forceinline__ void fwd_layer(
    const float* __restrict__ Wg, const float* __restrict__ bg,
    const float* __restrict__ Xs, int K,
    float* __restrict__ Ys, int cg, int ag)
{
    float4 bv = *reinterpret_cast<const float4*>(bg + cg * 4);
    float acc[4][4];
#pragma unroll
    for (int ai = 0; ai < 4; ai++) {
        acc[ai][0] = bv.x; acc[ai][1] = bv.y; acc[ai][2] = bv.z; acc[ai][3] = bv.w;
    }
    for (int k = 0; k < K; k++) {
        float4 w = __ldg(reinterpret_cast<const float4*>(Wg + k * HID) + cg);
#pragma unroll
        for (int ai = 0; ai < 4; ai++) {
            float x = Xs[(ag * 4 + ai) * K + k];
            acc[ai][0] += x * w.x; acc[ai][1] += x * w.y;
            acc[ai][2] += x * w.z; acc[ai][3] += x * w.w;
        }
    }
#pragma unroll
    for (int ai = 0; ai < 4; ai++)
#pragma unroll
        for (int jj = 0; jj < 4; jj++)
            Ys[(ag * 4 + ai) * HID + cg * 4 + jj] = tanhf(acc[ai][jj]);
}

// out[a][m] = sum_k Ds[a][k] * Wg[m][k]   (Wg row-major, row length HID)
// Mrows = number of valid output rows (HID or DIN); extra rows staged as 0.
__device__ __forceinline__ void bwd_gemm(
    const float* __restrict__ Wg, int Mrows,
    const float* __restrict__ Ds, float* __restrict__ Wsh,
    int tid, int cg, int ag, float acc[4][4])
{
#pragma unroll
    for (int ai = 0; ai < 4; ai++)
#pragma unroll
        for (int mm = 0; mm < 4; mm++) acc[ai][mm] = 0.f;

    for (int kc = 0; kc < HID; kc += 16) {
        __syncthreads();
        for (int idx = tid; idx < HID * 16; idx += NTHR) {
            int m = idx >> 4, kk = idx & 15;
            Wsh[m * 17 + kk] = (m < Mrows) ? __ldg(Wg + m * HID + kc + kk) : 0.f;
        }
        __syncthreads();
#pragma unroll
        for (int kk = 0; kk < 16; kk++) {
            float wv[4];
#pragma unroll
            for (int mm = 0; mm < 4; mm++)
                wv[mm] = Wsh[(cg + 32 * mm) * 17 + kk];
#pragma unroll
            for (int ai = 0; ai < 4; ai++) {
                float d = Ds[(ag * 4 + ai) * HID + kc + kk];
#pragma unroll
                for (int mm = 0; mm < 4; mm++) acc[ai][mm] += d * wv[mm];
            }
        }
    }
}

__global__ __launch_bounds__(NTHR) void k_mlp(
    const int* __restrict__ z, const float* __restrict__ fp,
    const int* __restrict__ image_idx,
    const float* __restrict__ W1, const float* __restrict__ b1,
    const float* __restrict__ W2, const float* __restrict__ b2,
    const float* __restrict__ W3, const float* __restrict__ b3,
    const float* __restrict__ W4, const float* __restrict__ b4,
    float* __restrict__ out_energy)
{
    __shared__ float fp_s[TILE * DIN];
    __shared__ float h1_s[TILE * HID];
    __shared__ float h2_s[TILE * HID];
    __shared__ float h3_s[TILE * HID];
    __shared__ float Ws[HID * 17];
    __shared__ int   s_aid[TILE];
    __shared__ int   s_e;

    int tid = threadIdx.x;
    int cg = tid & 31, ag = tid >> 5;

    if (tid == 0) s_e = -1;
    __syncthreads();
    if (tid < TILE) {
        int a = perm_d[blockIdx.x * TILE + tid];
        s_aid[tid] = a;
        if (a >= 0) s_e = elem_of(z[a]);   // all valid atoms in block share element
    }
    __syncthreads();
    if (s_e < 0) return;                   // all-padding block
    int e = s_e;

    // stage fingerprints (zeros for padding atoms)
    for (int idx = tid; idx < TILE * DIN; idx += NTHR) {
        int a = idx / DIN, i = idx - a * DIN;
        int aid = s_aid[a];
        fp_s[idx] = (aid >= 0) ? __ldg(fp + aid * DIN + i) : 0.f;
    }
    __syncthreads();

    const float* W1e = W1 + e * DIN * HID;
    const float* W2e = W2 + e * HID * HID;
    const float* W3e = W3 + e * HID * HID;
    const float* W4e = W4 + e * HID;

    // ---- forward ----
    fwd_layer(W1e, b1 + e * HID, fp_s, DIN, h1_s, cg, ag); __syncthreads();
    fwd_layer(W2e, b2 + e * HID, h1_s, HID, h2_s, cg, ag); __syncthreads();
    fwd_layer(W3e, b3 + e * HID, h2_s, HID, h3_s, cg, ag); __syncthreads();

    // ---- output layer + energy scatter (warp ag handles atoms ag*4..+3) ----
#pragma unroll
    for (int ai = 0; ai < 4; ai++) {
        int a = ag * 4 + ai;
        float p = 0.f;
#pragma unroll
        for (int q = 0; q < 4; q++) {
            int j = cg + 32 * q;
            p += h3_s[a * HID + j] * __ldg(W4e + j);
        }
#pragma unroll
        for (int o = 16; o; o >>= 1) p += __shfl_xor_sync(0xffffffffu, p, o);
        if (cg == 0) {
            int aid = s_aid[a];
            if (aid >= 0)
                atomicAdd(&out_energy[__ldg(image_idx + aid)], p + __ldg(b4 + e));
        }
    }
    __syncthreads();

    // dp3 = W4[j] * (1 - h3^2)  (in place)
    for (int idx = tid; idx < TILE * HID; idx += NTHR) {
        int j = idx & (HID - 1);
        float h = h3_s[idx];
        h3_s[idx] = __ldg(W4e + j) * (1.f - h * h);
    }
    // (bwd_gemm starts with __syncthreads)

    float acc[4][4];

    // dh2 = dp3 @ W3^T ; dp2 = dh2 * (1 - h2^2) in place
    bwd_gemm(W3e, HID, h3_s, Ws, tid, cg, ag, acc);
#pragma unroll
    for (int ai = 0; ai < 4; ai++)
#pragma unroll
        for (int mm = 0; mm < 4; mm++) {
            int a = ag * 4 + ai, j = cg + 32 * mm;
            float h = h2_s[a * HID + j];
            h2_s[a * HID + j] = acc[ai][mm] * (1.f - h * h);
        }

    // dh1 = dp2 @ W2^T ; dp1 = dh1 * (1 - h1^2) in place
    bwd_gemm(W2e, HID, h2_s, Ws, tid, cg, ag, acc);
#pragma unroll
    for (int ai = 0; ai < 4; ai++)
#pragma unroll
        for (int mm = 0; mm < 4; mm++) {
            int a = ag * 4 + ai, j = cg + 32 * mm;
            float h = h1_s[a * HID + j];
            h1_s[a * HID + j] = acc[ai][mm] * (1.f - h * h);
        }

    // g = dp1 @ W1^T  (W1 rows i in 0..119)
    bwd_gemm(W1e, DIN, h1_s, Ws, tid, cg, ag, acc);
#pragma unroll
    for (int mm = 0; mm < 4; mm++) {
        int i = cg + 32 * mm;
        if (i < DIN) {
#pragma unroll
            for (int ai = 0; ai < 4; ai++) {
                int aid = s_aid[ag * 4 + ai];
                if (aid >= 0) g_flat_d[aid * DIN + i] = acc[ai][mm];
            }
        }
    }
}

// ---------------- sparse force scatter: forces[col] -= val * g[row] ------
__global__ void k_scatter(const int* __restrict__ rows,
                          const int* __restrict__ cols,
                          const float* __restrict__ vals,
                          float* __restrict__ forces, int nnz)
{
    int t = blockIdx.x * blockDim.x + threadIdx.x;
    if (t < nnz) {
        float v = __ldg(vals + t) * g_flat_d[__ldg(rows + t)];
        atomicAdd(forces + __ldg(cols + t), -v);
    }
}

// ---------------- launch --------------------------------------------------
extern "C" void kernel_launch(void* const* d_in, const int* in_sizes, int n_in,
                              void* d_out, int out_size)
{
    const int*   z    = (const int*)  d_in[0];
    const float* fp   = (const float*)d_in[1];
    const int*   img  = (const int*)  d_in[2];
    const int*   rows = (const int*)  d_in[3];
    const int*   cols = (const int*)  d_in[4];
    const float* vals = (const float*)d_in[5];
    // n_mol may or may not appear as a device scalar at index 6; detect by size.
    int base = (in_sizes[6] == NELEM * DIN * HID) ? 6 : 7;
    const float* W1 = (const float*)d_in[base + 0];
    const float* b1 = (const float*)d_in[base + 1];
    const float* W2 = (const float*)d_in[base + 2];
    const float* b2 = (const float*)d_in[base + 3];
    const float* W3 = (const float*)d_in[base + 4];
    const float* b3 = (const float*)d_in[base + 5];
    const float* W4 = (const float*)d_in[base + 6];
    const float* b4 = (const float*)d_in[base + 7];

    float* out    = (float*)d_out;
    float* energy = out;            // [NMOL]
    float* forces = out + NMOL;     // [3*N_ATOMS]
    int nnz = in_sizes[3];

    int tot = NMOL + 3 * N_ATOMS;
    k_init   <<<(tot + 255) / 256, 256>>>(out);
    k_count  <<<(N_ATOMS + 255) / 256, 256>>>(z);
    k_offsets<<<1, 1>>>();
    k_build  <<<(N_ATOMS + 255) / 256, 256>>>(z);
    k_mlp    <<<NBLK, NTHR>>>(z, fp, img, W1, b1, W2, b2, W3, b3, W4, b4, energy);
    k_scatter<<<(nnz + 255) / 256, 256>>>(rows, cols, vals, forces, nnz);
}